// round 10
// baseline (speedup 1.0000x reference)
#include <cuda_runtime.h>
#include <mma.h>
#include <math.h>

using namespace nvcuda;

#define NN 20000
#define EE 320000
#define ETOT 340000      // EE + NN self loops
#define ELN 100000

// ---------------- scratch (device globals; no allocation allowed) ----------
__device__ float g_xl1[NN*512];
__device__ float g_xr1[NN*512];
__device__ float g_z1 [NN*512];
__device__ float g_xl2[NN*128];
__device__ float g_xr2[NN*128];
__device__ float g_z2 [NN*128];
__device__ int   g_deg[NN];
__device__ int   g_rowptr[NN+1];
__device__ int   g_cursor[NN];
__device__ int   g_slist[ETOT];   // src node per CSR slot (dst implicit by row)

__device__ __forceinline__ float gelu_t(float x){
  float u = 0.7978845608028654f*(x + 0.044715f*x*x*x);
  return 0.5f*x*(1.0f+tanhf(u));
}

// ---------------- CSR build --------------------------------------------------
__global__ void count_kernel(const int* __restrict__ ei){
  int e=blockIdx.x*blockDim.x+threadIdx.x;
  if(e>=ETOT)return;
  int dst = (e<EE) ? ei[EE+e] : (e-EE);
  atomicAdd(&g_deg[dst],1);
}

__global__ void scan_kernel(){
  __shared__ int sums[1024];
  int tid=threadIdx.x;
  const int CH=(NN+1023)/1024;           // 20
  int start=tid*CH;
  int s=0;
  for(int i=0;i<CH;i++){int idx=start+i; if(idx<NN) s+=g_deg[idx];}
  sums[tid]=s; __syncthreads();
  for(int off=1;off<1024;off<<=1){
    int v=sums[tid];
    int add=(tid>=off)?sums[tid-off]:0;
    __syncthreads();
    sums[tid]=v+add;
    __syncthreads();
  }
  int run=(tid==0)?0:sums[tid-1];
  for(int i=0;i<CH;i++){
    int idx=start+i;
    if(idx<NN){ g_rowptr[idx]=run; run+=g_deg[idx]; }
  }
  if(tid==0) g_rowptr[NN]=sums[1023];
}

__global__ void scatter_kernel(const int* __restrict__ ei){
  int e=blockIdx.x*blockDim.x+threadIdx.x;
  if(e>=ETOT)return;
  int src,dst;
  if(e<EE){ src=ei[e]; dst=ei[EE+e]; } else { src=e-EE; dst=src; }
  int pos=atomicAdd(&g_cursor[dst],1);
  g_slist[g_rowptr[dst]+pos]=src;
}

// ---------------- pipelined TF32 WMMA GEMM (R5 measured-best shape) ----------
#define BM 128
#define BN 128
#define BK 16

__device__ __forceinline__ void ldg_A(const float* __restrict__ A,int M,int K,
                                      int row0,int k0,int tid,float4* pa){
  #pragma unroll
  for(int it=0;it<2;it++){
    int i=tid+256*it;
    int r=i>>2, c4=(i&3)*4;
    int gr=row0+r;
    float4 v={0.f,0.f,0.f,0.f};
    if(gr<M) v=*(const float4*)&A[(size_t)gr*K + k0 + c4];
    pa[it]=v;
  }
}
__device__ __forceinline__ void sts_A(float (*As)[BK+4],int tid,const float4* pa){
  #pragma unroll
  for(int it=0;it<2;it++){
    int i=tid+256*it;
    int r=i>>2, c4=(i&3)*4;
    As[r][c4+0]=wmma::__float_to_tf32(pa[it].x);
    As[r][c4+1]=wmma::__float_to_tf32(pa[it].y);
    As[r][c4+2]=wmma::__float_to_tf32(pa[it].z);
    As[r][c4+3]=wmma::__float_to_tf32(pa[it].w);
  }
}
__device__ __forceinline__ void ldg_B(const float* __restrict__ B,int N,
                                      int col0,int k0,int tid,float4* pb){
  #pragma unroll
  for(int it=0;it<2;it++){
    int i=tid+256*it;
    int r=i>>5, c4=(i&31)*4;
    pb[it]=*(const float4*)&B[(size_t)(k0+r)*N + col0 + c4];
  }
}
__device__ __forceinline__ void sts_B(float (*Bs)[BN+4],int tid,const float4* pb){
  #pragma unroll
  for(int it=0;it<2;it++){
    int i=tid+256*it;
    int r=i>>5, c4=(i&31)*4;
    Bs[r][c4+0]=wmma::__float_to_tf32(pb[it].x);
    Bs[r][c4+1]=wmma::__float_to_tf32(pb[it].y);
    Bs[r][c4+2]=wmma::__float_to_tf32(pb[it].z);
    Bs[r][c4+3]=wmma::__float_to_tf32(pb[it].w);
  }
}

// C_z = A @ B_z + bias_z  (z = blockIdx.z selects B/bias/C; A shared)
__global__ void wmma_gemm2(const float* __restrict__ A,
                           const float* __restrict__ B1, const float* __restrict__ bias1_,
                           float* __restrict__ C1,
                           const float* __restrict__ B2, const float* __restrict__ bias2_,
                           float* __restrict__ C2,
                           int M, int K, int N){
  const float* B    = blockIdx.z ? B2 : B1;
  const float* bias = blockIdx.z ? bias2_ : bias1_;
  float*       C    = blockIdx.z ? C2 : C1;

  __shared__ float As[2][BM][BK+4];
  __shared__ float Bs[2][BK][BN+4];

  int tid=threadIdx.x;
  int warp=tid>>5, lane=tid&31;
  int wm=warp>>1, wn=warp&1;
  int row0=blockIdx.y*BM, col0=blockIdx.x*BN;

  // stage bias (replicated over 16 rows) in Bs[0]; init accumulators from it
  for(int i=tid;i<16*BN;i+=256){ int r=i>>7, c=i&127; Bs[0][r][c]=bias[col0+c]; }
  __syncthreads();
  wmma::fragment<wmma::accumulator,16,16,8,float> acc[2][4];
  #pragma unroll
  for(int i=0;i<2;i++)
    #pragma unroll
    for(int j=0;j<4;j++)
      wmma::load_matrix_sync(acc[i][j], &Bs[0][0][wn*64+j*16], BN+4, wmma::mem_row_major);
  __syncthreads();

  float4 pa[2], pb[2];
  ldg_A(A,M,K,row0,0,tid,pa);
  ldg_B(B,N,col0,0,tid,pb);
  sts_A(As[0],tid,pa);
  sts_B(Bs[0],tid,pb);
  __syncthreads();

  int nk=K/BK;
  for(int kt=0;kt<nk;kt++){
    int cur=kt&1;
    if(kt+1<nk){
      ldg_A(A,M,K,row0,(kt+1)*BK,tid,pa);
      ldg_B(B,N,col0,(kt+1)*BK,tid,pb);
    }
    #pragma unroll
    for(int ks=0;ks<BK;ks+=8){
      wmma::fragment<wmma::matrix_a,16,16,8,wmma::precision::tf32,wmma::row_major> af[2];
      wmma::fragment<wmma::matrix_b,16,16,8,wmma::precision::tf32,wmma::row_major> bf[4];
      #pragma unroll
      for(int i=0;i<2;i++) wmma::load_matrix_sync(af[i], &As[cur][wm*32+i*16][ks], BK+4);
      #pragma unroll
      for(int j=0;j<4;j++) wmma::load_matrix_sync(bf[j], &Bs[cur][ks][wn*64+j*16], BN+4);
      #pragma unroll
      for(int i=0;i<2;i++)
        #pragma unroll
        for(int j=0;j<4;j++) wmma::mma_sync(acc[i][j],af[i],bf[j],acc[i][j]);
    }
    if(kt+1<nk){
      sts_A(As[cur^1],tid,pa);
      sts_B(Bs[cur^1],tid,pb);
      __syncthreads();
    }
  }

  if(row0+BM<=M){
    // fast path: direct global store (bias already in acc)
    #pragma unroll
    for(int i=0;i<2;i++)
      #pragma unroll
      for(int j=0;j<4;j++){
        int r0=row0+wm*32+i*16, c0=col0+wn*64+j*16;
        wmma::store_matrix_sync(&C[(size_t)r0*N+c0], acc[i][j], N, wmma::mem_row_major);
      }
  } else {
    // ragged tail: stage via As[0] (last mma read buffer 1; per-warp region)
    float* St = &As[0][warp*16][0];     // 16x20 per warp
    #pragma unroll
    for(int i=0;i<2;i++)
      #pragma unroll
      for(int j=0;j<4;j++){
        wmma::store_matrix_sync(St, acc[i][j], 20, wmma::mem_row_major);
        __syncwarp();
        int r0=row0+wm*32+i*16, c0=col0+wn*64+j*16;
        #pragma unroll
        for(int t=lane;t<256;t+=32){
          int rr=t>>4, cc=t&15;
          int gr=r0+rr;
          if(gr<M) C[(size_t)gr*N+c0+cc]=St[rr*20+cc];
        }
        __syncwarp();
      }
  }
}

// Decoder fully fused (pipelined): out[r] = dot( gelu( cat(z2[eli0[r]],z2[eli1[r]]) @ Wd1 + bd1 ), Wd2 ) + bd2
__global__ void wmma_gemm_dec(const int* __restrict__ eli,
                              const float* __restrict__ B,    // Wd1 [256x128]
                              const float* __restrict__ bias, // bd1 [128]
                              const float* __restrict__ Wd2,  // [128]
                              const float* __restrict__ bd2,  // [1]
                              float* __restrict__ out){
  const int K=256, N=128;
  __shared__ float As[2][BM][BK+4];
  __shared__ float Bs[2][BK][BN+4];
  __shared__ float rowsum[128];
  __shared__ float w2s[128];
  __shared__ float bias_s[128];

  int tid=threadIdx.x;
  int warp=tid>>5, lane=tid&31;
  int wm=warp>>1, wn=warp&1;
  int row0=blockIdx.y*BM;

  if(tid<128){ rowsum[tid]=0.f; w2s[tid]=Wd2[tid]; bias_s[tid]=bias[tid]; }

  // prefetch gather indices once (k-invariant per half)
  int r_ = tid>>2;
  int gr0=row0+r_, gr1=row0+r_+64;
  int n00 = (gr0<ELN)? eli[gr0]      : 0;
  int n01 = (gr1<ELN)? eli[gr1]      : 0;
  int n10 = (gr0<ELN)? eli[ELN+gr0]  : 0;
  int n11 = (gr1<ELN)? eli[ELN+gr1]  : 0;
  int c4_ = (tid&3)*4;

  wmma::fragment<wmma::accumulator,16,16,8,float> acc[2][4];
  #pragma unroll
  for(int i=0;i<2;i++)
    #pragma unroll
    for(int j=0;j<4;j++) wmma::fill_fragment(acc[i][j],0.f);

  float4 pa[2], pb[2];
  {
    pa[0]=(gr0<ELN)? *(const float4*)&g_z2[(size_t)n00*128 + c4_] : make_float4(0,0,0,0);
    pa[1]=(gr1<ELN)? *(const float4*)&g_z2[(size_t)n01*128 + c4_] : make_float4(0,0,0,0);
  }
  ldg_B(B,N,0,0,tid,pb);
  sts_A(As[0],tid,pa);
  sts_B(Bs[0],tid,pb);
  __syncthreads();

  const int nk=K/BK;   // 16
  for(int kt=0;kt<nk;kt++){
    int cur=kt&1;
    if(kt+1<nk){
      int k0=(kt+1)*BK;
      int half = (k0>=128);
      int koff = half? (k0-128) : k0;
      int na = half? n10 : n00;
      int nb = half? n11 : n01;
      pa[0]=(gr0<ELN)? *(const float4*)&g_z2[(size_t)na*128 + koff + c4_] : make_float4(0,0,0,0);
      pa[1]=(gr1<ELN)? *(const float4*)&g_z2[(size_t)nb*128 + koff + c4_] : make_float4(0,0,0,0);
      ldg_B(B,N,0,k0,tid,pb);
    }
    #pragma unroll
    for(int ks=0;ks<BK;ks+=8){
      wmma::fragment<wmma::matrix_a,16,16,8,wmma::precision::tf32,wmma::row_major> af[2];
      wmma::fragment<wmma::matrix_b,16,16,8,wmma::precision::tf32,wmma::row_major> bf[4];
      #pragma unroll
      for(int i=0;i<2;i++) wmma::load_matrix_sync(af[i], &As[cur][wm*32+i*16][ks], BK+4);
      #pragma unroll
      for(int j=0;j<4;j++) wmma::load_matrix_sync(bf[j], &Bs[cur][ks][wn*64+j*16], BN+4);
      #pragma unroll
      for(int i=0;i<2;i++)
        #pragma unroll
        for(int j=0;j<4;j++) wmma::mma_sync(acc[i][j],af[i],bf[j],acc[i][j]);
    }
    if(kt+1<nk){
      sts_A(As[cur^1],tid,pa);
      sts_B(Bs[cur^1],tid,pb);
      __syncthreads();
    }
  }

  // epilogue: gelu(acc+bias) dotted with Wd2, per-row reduction.
  float* St = &As[0][warp*16][0];
  float rowpart=0.f;               // lane owns local row wm*32+lane
  int li = lane>>4;
  int rr = lane&15;
  #pragma unroll
  for(int i=0;i<2;i++)
    #pragma unroll
    for(int j=0;j<4;j++){
      wmma::store_matrix_sync(St, acc[i][j], 20, wmma::mem_row_major);
      __syncwarp();
      if(li==i){
        int c0=wn*64+j*16;
        #pragma unroll
        for(int cc=0;cc<16;cc++){
          int gc=c0+cc;
          rowpart += gelu_t(St[rr*20+cc]+bias_s[gc])*w2s[gc];
        }
      }
      __syncwarp();
    }
  atomicAdd(&rowsum[wm*32+lane], rowpart);
  __syncthreads();
  if(tid<128){
    int gr=row0+tid;
    if(gr<ELN) out[gr]=rowsum[tid]+bd2[0];
  }
}

// ---------------- fused GATv2 layer 1 (H=4, C=128), 2-stream online softmax --
__global__ void gat1_fused(const float* __restrict__ att1, const float* __restrict__ bias1){
  int node=blockIdx.x;
  int w=threadIdx.x>>5, lane=threadIdx.x&31;
  float4 xd = ((const float4*)(g_xr1+(size_t)node*512 + w*128))[lane];
  float4 av = ((const float4*)(att1 + w*128))[lane];
  float m0=-1e30f, s0=0.f, m1=-1e30f, s1=0.f;
  float4 a0={0.f,0.f,0.f,0.f}, a1={0.f,0.f,0.f,0.f};
  int b=g_rowptr[node], en=g_rowptr[node+1];
  int i=b;
  for(; i+1<en; i+=2){
    int src0=g_slist[i], src1=g_slist[i+1];
    float4 x0 = ((const float4*)(g_xl1+(size_t)src0*512 + w*128))[lane];
    float4 x1 = ((const float4*)(g_xl1+(size_t)src1*512 + w*128))[lane];
    float u,p0,p1;
    u=x0.x+xd.x; u=u>0.f?u:0.2f*u; p0 =u*av.x;
    u=x0.y+xd.y; u=u>0.f?u:0.2f*u; p0+=u*av.y;
    u=x0.z+xd.z; u=u>0.f?u:0.2f*u; p0+=u*av.z;
    u=x0.w+xd.w; u=u>0.f?u:0.2f*u; p0+=u*av.w;
    u=x1.x+xd.x; u=u>0.f?u:0.2f*u; p1 =u*av.x;
    u=x1.y+xd.y; u=u>0.f?u:0.2f*u; p1+=u*av.y;
    u=x1.z+xd.z; u=u>0.f?u:0.2f*u; p1+=u*av.z;
    u=x1.w+xd.w; u=u>0.f?u:0.2f*u; p1+=u*av.w;
    #pragma unroll
    for(int o=16;o;o>>=1){
      p0 += __shfl_xor_sync(0xffffffffu,p0,o);
      p1 += __shfl_xor_sync(0xffffffffu,p1,o);
    }
    float nm0=fmaxf(m0,p0), sc0=__expf(m0-nm0), e0=__expf(p0-nm0);
    float nm1=fmaxf(m1,p1), sc1=__expf(m1-nm1), e1=__expf(p1-nm1);
    s0=s0*sc0+e0; s1=s1*sc1+e1;
    a0.x=a0.x*sc0+e0*x0.x; a0.y=a0.y*sc0+e0*x0.y; a0.z=a0.z*sc0+e0*x0.z; a0.w=a0.w*sc0+e0*x0.w;
    a1.x=a1.x*sc1+e1*x1.x; a1.y=a1.y*sc1+e1*x1.y; a1.z=a1.z*sc1+e1*x1.z; a1.w=a1.w*sc1+e1*x1.w;
    m0=nm0; m1=nm1;
  }
  if(i<en){
    int src0=g_slist[i];
    float4 x0 = ((const float4*)(g_xl1+(size_t)src0*512 + w*128))[lane];
    float u,p0;
    u=x0.x+xd.x; u=u>0.f?u:0.2f*u; p0 =u*av.x;
    u=x0.y+xd.y; u=u>0.f?u:0.2f*u; p0+=u*av.y;
    u=x0.z+xd.z; u=u>0.f?u:0.2f*u; p0+=u*av.z;
    u=x0.w+xd.w; u=u>0.f?u:0.2f*u; p0+=u*av.w;
    #pragma unroll
    for(int o=16;o;o>>=1) p0 += __shfl_xor_sync(0xffffffffu,p0,o);
    float nm0=fmaxf(m0,p0), sc0=__expf(m0-nm0), e0=__expf(p0-nm0);
    s0=s0*sc0+e0;
    a0.x=a0.x*sc0+e0*x0.x; a0.y=a0.y*sc0+e0*x0.y; a0.z=a0.z*sc0+e0*x0.z; a0.w=a0.w*sc0+e0*x0.w;
    m0=nm0;
  }
  // merge streams
  float M=fmaxf(m0,m1);
  float c0=__expf(m0-M), c1=__expf(m1-M);
  float S=s0*c0+s1*c1;
  float inv=1.f/S;
  float4 bv = ((const float4*)(bias1 + w*128))[lane];
  float4 o;
  o.x = gelu_t((a0.x*c0+a1.x*c1)*inv + bv.x);
  o.y = gelu_t((a0.y*c0+a1.y*c1)*inv + bv.y);
  o.z = gelu_t((a0.z*c0+a1.z*c1)*inv + bv.z);
  o.w = gelu_t((a0.w*c0+a1.w*c1)*inv + bv.w);
  ((float4*)(g_z1+(size_t)node*512 + w*128))[lane] = o;
}

// ---------------- fused GATv2 layer 2 (H=1, C=128), 4-way split-merge -------
__global__ void gat2_fused(const float* __restrict__ att2, const float* __restrict__ bias2){
  __shared__ float  sm_m[4], sm_s[4];
  __shared__ float4 sm_acc[4][32];
  int node=blockIdx.x;
  int w=threadIdx.x>>5, lane=threadIdx.x&31;
  float4 xd = ((const float4*)(g_xr2+(size_t)node*128))[lane];
  float4 av = ((const float4*)att2)[lane];
  float m=-1e30f, s=0.f;
  float4 acc={0.f,0.f,0.f,0.f};
  int b=g_rowptr[node], en=g_rowptr[node+1];
  for(int i=b+w;i<en;i+=4){
    int src = g_slist[i];
    float4 xs = ((const float4*)(g_xl2+(size_t)src*128))[lane];
    float u,part;
    u=xs.x+xd.x; u=u>0.f?u:0.2f*u; part =u*av.x;
    u=xs.y+xd.y; u=u>0.f?u:0.2f*u; part+=u*av.y;
    u=xs.z+xd.z; u=u>0.f?u:0.2f*u; part+=u*av.z;
    u=xs.w+xd.w; u=u>0.f?u:0.2f*u; part+=u*av.w;
    #pragma unroll
    for(int o=16;o;o>>=1) part += __shfl_xor_sync(0xffffffffu,part,o);
    float nm = fmaxf(m, part);
    float sc = __expf(m - nm);
    float p  = __expf(part - nm);
    s = s*sc + p;
    acc.x = acc.x*sc + p*xs.x;
    acc.y = acc.y*sc + p*xs.y;
    acc.z = acc.z*sc + p*xs.z;
    acc.w = acc.w*sc + p*xs.w;
    m = nm;
  }
  if(lane==0){ sm_m[w]=m; sm_s[w]=s; }
  sm_acc[w][lane]=acc;
  __syncthreads();
  if(w==0){
    float M = fmaxf(fmaxf(sm_m[0],sm_m[1]),fmaxf(sm_m[2],sm_m[3]));
    float S=0.f;
    float4 o={0.f,0.f,0.f,0.f};
    #pragma unroll
    for(int ww=0;ww<4;ww++){
      float sc=__expf(sm_m[ww]-M);
      S += sm_s[ww]*sc;
      float4 a=sm_acc[ww][lane];
      o.x+=a.x*sc; o.y+=a.y*sc; o.z+=a.z*sc; o.w+=a.w*sc;
    }
    float inv=1.f/S;
    float4 bv=((const float4*)bias2)[lane];
    float4 r;
    r.x=o.x*inv+bv.x; r.y=o.y*inv+bv.y; r.z=o.z*inv+bv.z; r.w=o.w*inv+bv.w;
    ((float4*)(g_z2+(size_t)node*128))[lane]=r;
  }
}

// ---------------- launch -----------------------------------------------------
extern "C" void kernel_launch(void* const* d_in, const int* in_sizes, int n_in,
                              void* d_out, int out_size){
  const float* x    =(const float*)d_in[0];
  const int*   ei   =(const int*  )d_in[1];
  const int*   eli  =(const int*  )d_in[2];
  const float* Wl1  =(const float*)d_in[3];
  const float* bl1  =(const float*)d_in[4];
  const float* Wr1  =(const float*)d_in[5];
  const float* br1  =(const float*)d_in[6];
  const float* att1 =(const float*)d_in[7];
  const float* bias1=(const float*)d_in[8];
  const float* Wl2  =(const float*)d_in[9];
  const float* bl2  =(const float*)d_in[10];
  const float* Wr2  =(const float*)d_in[11];
  const float* br2  =(const float*)d_in[12];
  const float* att2 =(const float*)d_in[13];
  const float* bias2=(const float*)d_in[14];
  const float* Wd1  =(const float*)d_in[15];
  const float* bd1  =(const float*)d_in[16];
  const float* Wd2  =(const float*)d_in[17];
  const float* bd2  =(const float*)d_in[18];
  float* out=(float*)d_out;

  float *p_xl1,*p_xr1,*p_z1,*p_xl2,*p_xr2;
  int  *p_deg,*p_cursor;
  cudaGetSymbolAddress((void**)&p_xl1, g_xl1);
  cudaGetSymbolAddress((void**)&p_xr1, g_xr1);
  cudaGetSymbolAddress((void**)&p_z1 , g_z1 );
  cudaGetSymbolAddress((void**)&p_xl2, g_xl2);
  cudaGetSymbolAddress((void**)&p_xr2, g_xr2);
  cudaGetSymbolAddress((void**)&p_deg, g_deg);
  cudaGetSymbolAddress((void**)&p_cursor, g_cursor);

  // fork a side stream for the CSR build so it overlaps the layer-1 GEMM.
  // (created per call and intentionally not destroyed while capture is active;
  //  kernel_launch runs only a handful of times, so the leak is bounded)
  cudaStream_t s1;
  cudaEvent_t ev_fork, ev_join;
  cudaStreamCreateWithFlags(&s1, cudaStreamNonBlocking);
  cudaEventCreateWithFlags(&ev_fork, cudaEventDisableTiming);
  cudaEventCreateWithFlags(&ev_join, cudaEventDisableTiming);

  cudaEventRecord(ev_fork, 0);              // fork point on the capture (legacy) stream
  cudaStreamWaitEvent(s1, ev_fork, 0);

  // CSR build on side stream
  cudaMemsetAsync(p_deg,    0, NN*sizeof(int), s1);
  cudaMemsetAsync(p_cursor, 0, NN*sizeof(int), s1);
  count_kernel  <<<(ETOT+255)/256,256,0,s1>>>(ei);
  scan_kernel   <<<1,1024,0,s1>>>();
  scatter_kernel<<<(ETOT+255)/256,256,0,s1>>>(ei);
  cudaEventRecord(ev_join, s1);

  // layer-1 node transforms on main stream (independent of CSR)
  wmma_gemm2<<<dim3(512/128,(NN+127)/128,2),256>>>(x, Wl1, bl1, p_xl1, Wr1, br1, p_xr1,
                                                   NN, 256, 512);

  // join: gat1 needs both GEMM results and the CSR
  cudaStreamWaitEvent(0, ev_join, 0);

  // layer-1 fused attention (online softmax + aggregate + gelu)
  gat1_fused<<<NN,128>>>(att1, bias1);

  // layer-2 node transforms
  wmma_gemm2<<<dim3(1,(NN+127)/128,2),256>>>(p_z1, Wl2, bl2, p_xl2, Wr2, br2, p_xr2,
                                             NN, 512, 128);
  // layer-2 fused attention
  gat2_fused<<<NN,128>>>(att2, bias2);

  // decoder: gather-fused GEMM + gelu + Wd2 dot, all in one kernel
  wmma_gemm_dec<<<dim3(1,(ELN+127)/128),256>>>(eli, Wd1, bd1, Wd2, bd2, out);
}

// round 13
// speedup vs baseline: 1.1320x; 1.1320x over previous
#include <cuda_runtime.h>
#include <mma.h>
#include <math.h>
#include <cstdint>

using namespace nvcuda;

#define NN 20000
#define EE 320000
#define ETOT 340000      // EE + NN self loops
#define ELN 100000

// ---------------- scratch (device globals; no allocation allowed) ----------
__device__ float g_xl1[NN*512];
__device__ float g_xr1[NN*512];
__device__ float g_z1 [NN*512];
__device__ float g_xl2[NN*128];
__device__ float g_xr2[NN*128];
__device__ float g_z2 [NN*128];
__device__ int   g_deg[NN];
__device__ int   g_rowptr[NN+1];
__device__ int   g_cursor[NN];
__device__ int   g_slist[ETOT];   // src node per CSR slot (dst implicit by row)

__device__ __forceinline__ float gelu_t(float x){
  float u = 0.7978845608028654f*(x + 0.044715f*x*x*x);
  return 0.5f*x*(1.0f+tanhf(u));
}

// ---------------- cp.async helpers ------------------------------------------
__device__ __forceinline__ void cp16(uint32_t s, const void* g){
  asm volatile("cp.async.cg.shared.global [%0], [%1], 16;\n"::"r"(s),"l"(g));
}
// pred==0 -> zero-fill 16B (no src read)
__device__ __forceinline__ void cp16z(uint32_t s, const void* g, int pred){
  int sz = pred ? 16 : 0;
  asm volatile("cp.async.cg.shared.global [%0], [%1], 16, %2;\n"::"r"(s),"l"(g),"r"(sz));
}
#define CP_COMMIT() asm volatile("cp.async.commit_group;\n")
#define CP_WAIT(n)  asm volatile("cp.async.wait_group %0;\n"::"n"(n))
#define SMEM_U32(p) ((uint32_t)__cvta_generic_to_shared(p))

// ---------------- CSR build --------------------------------------------------
__global__ void init_kernel(){
  int t=blockIdx.x*blockDim.x+threadIdx.x;
  if(t<NN){ g_deg[t]=0; g_cursor[t]=0; }
}

__global__ void count_kernel(const int* __restrict__ ei){
  int e=blockIdx.x*blockDim.x+threadIdx.x;
  if(e>=ETOT)return;
  int dst = (e<EE) ? ei[EE+e] : (e-EE);
  atomicAdd(&g_deg[dst],1);
}

__global__ void scan_kernel(){
  __shared__ int sums[1024];
  int tid=threadIdx.x;
  const int CH=(NN+1023)/1024;           // 20
  int start=tid*CH;
  int s=0;
  for(int i=0;i<CH;i++){int idx=start+i; if(idx<NN) s+=g_deg[idx];}
  sums[tid]=s; __syncthreads();
  for(int off=1;off<1024;off<<=1){
    int v=sums[tid];
    int add=(tid>=off)?sums[tid-off]:0;
    __syncthreads();
    sums[tid]=v+add;
    __syncthreads();
  }
  int run=(tid==0)?0:sums[tid-1];
  for(int i=0;i<CH;i++){
    int idx=start+i;
    if(idx<NN){ g_rowptr[idx]=run; run+=g_deg[idx]; }
  }
  if(tid==0) g_rowptr[NN]=sums[1023];
}

__global__ void scatter_kernel(const int* __restrict__ ei){
  int e=blockIdx.x*blockDim.x+threadIdx.x;
  if(e>=ETOT)return;
  int src,dst;
  if(e<EE){ src=ei[e]; dst=ei[EE+e]; } else { src=e-EE; dst=src; }
  int pos=atomicAdd(&g_cursor[dst],1);
  g_slist[g_rowptr[dst]+pos]=src;
}

// ---------------- cp.async TF32 WMMA GEMM, 2-stage pipeline ------------------
#define BM 128
#define BN 128
#define BK 16

// round fragment elements to tf32 (keeps numerics = explicit-convert path)
template<class Frag>
__device__ __forceinline__ void frag_to_tf32(Frag& f){
  #pragma unroll
  for(int t=0;t<f.num_elements;t++) f.x[t]=wmma::__float_to_tf32(f.x[t]);
}

// C_z = A @ B_z + bias_z  (z = blockIdx.z selects B/bias/C; A shared)
__global__ __launch_bounds__(256,2)
void wmma_gemm2(const float* __restrict__ A,
                const float* __restrict__ B1, const float* __restrict__ bias1_,
                float* __restrict__ C1,
                const float* __restrict__ B2, const float* __restrict__ bias2_,
                float* __restrict__ C2,
                int M, int K, int N){
  const float* B    = blockIdx.z ? B2 : B1;
  const float* bias = blockIdx.z ? bias2_ : bias1_;
  float*       C    = blockIdx.z ? C2 : C1;

  __shared__ float As[2][BM][BK+4];
  __shared__ float Bs[2][BK][BN+4];

  int tid=threadIdx.x;
  int warp=tid>>5, lane=tid&31;
  int wm=warp>>1, wn=warp&1;
  int row0=blockIdx.y*BM, col0=blockIdx.x*BN;

  // bias -> accumulators via Bs[0] staging (before any cp.async touches it)
  for(int i=tid;i<16*BN;i+=256){ int r=i>>7, c=i&127; Bs[0][r][c]=bias[col0+c]; }
  __syncthreads();
  wmma::fragment<wmma::accumulator,16,16,8,float> acc[2][4];
  #pragma unroll
  for(int i=0;i<2;i++)
    #pragma unroll
    for(int j=0;j<4;j++)
      wmma::load_matrix_sync(acc[i][j], &Bs[0][0][wn*64+j*16], BN+4, wmma::mem_row_major);
  __syncthreads();

  // per-thread chunk coords (2 chunks of A, 2 of B per stage)
  int ra0=tid>>2,        ca=(tid&3)*4;       // A rows tid>>2 and +64
  int rb0=tid>>5,        cb=(tid&31)*4;      // B rows tid>>5 and +8

  // issue one stage's copies
  #define ISSUE_STAGE(st,k0) do{                                              \
    int gra0=row0+ra0, gra1=row0+ra0+64;                                      \
    cp16z(SMEM_U32(&As[st][ra0   ][ca]),                                      \
          &A[(size_t)min(gra0,M-1)*K + (k0) + ca], gra0<M);                   \
    cp16z(SMEM_U32(&As[st][ra0+64][ca]),                                      \
          &A[(size_t)min(gra1,M-1)*K + (k0) + ca], gra1<M);                   \
    cp16(SMEM_U32(&Bs[st][rb0  ][cb]),                                        \
         &B[(size_t)((k0)+rb0  )*N + col0 + cb]);                             \
    cp16(SMEM_U32(&Bs[st][rb0+8][cb]),                                        \
         &B[(size_t)((k0)+rb0+8)*N + col0 + cb]);                             \
    CP_COMMIT();                                                              \
  }while(0)

  int nk=K/BK;
  ISSUE_STAGE(0,0);
  if(nk>1) ISSUE_STAGE(1,BK);

  for(int kt=0;kt<nk;kt++){
    int cur=kt&1;
    if(kt+1<nk){ CP_WAIT(1); } else { CP_WAIT(0); }
    __syncthreads();
    #pragma unroll
    for(int ks=0;ks<BK;ks+=8){
      wmma::fragment<wmma::matrix_a,16,16,8,wmma::precision::tf32,wmma::row_major> af[2];
      wmma::fragment<wmma::matrix_b,16,16,8,wmma::precision::tf32,wmma::row_major> bf[4];
      #pragma unroll
      for(int i=0;i<2;i++){ wmma::load_matrix_sync(af[i], &As[cur][wm*32+i*16][ks], BK+4); frag_to_tf32(af[i]); }
      #pragma unroll
      for(int j=0;j<4;j++){ wmma::load_matrix_sync(bf[j], &Bs[cur][ks][wn*64+j*16], BN+4); frag_to_tf32(bf[j]); }
      #pragma unroll
      for(int i=0;i<2;i++)
        #pragma unroll
        for(int j=0;j<4;j++) wmma::mma_sync(acc[i][j],af[i],bf[j],acc[i][j]);
    }
    __syncthreads();                    // all warps done reading buffer `cur`
    if(kt+2<nk) ISSUE_STAGE(cur,(kt+2)*BK);
  }
  #undef ISSUE_STAGE

  if(row0+BM<=M){
    // fast path: direct global store (bias already in acc)
    #pragma unroll
    for(int i=0;i<2;i++)
      #pragma unroll
      for(int j=0;j<4;j++){
        int r0=row0+wm*32+i*16, c0=col0+wn*64+j*16;
        wmma::store_matrix_sync(&C[(size_t)r0*N+c0], acc[i][j], N, wmma::mem_row_major);
      }
  } else {
    // ragged tail: stage via As[0] per-warp regions
    __syncthreads();
    float* St = &As[0][warp*16][0];     // 16x20 per warp
    #pragma unroll
    for(int i=0;i<2;i++)
      #pragma unroll
      for(int j=0;j<4;j++){
        wmma::store_matrix_sync(St, acc[i][j], 20, wmma::mem_row_major);
        __syncwarp();
        int r0=row0+wm*32+i*16, c0=col0+wn*64+j*16;
        #pragma unroll
        for(int t=lane;t<256;t+=32){
          int rr=t>>4, cc=t&15;
          int gr=r0+rr;
          if(gr<M) C[(size_t)gr*N+c0+cc]=St[rr*20+cc];
        }
        __syncwarp();
      }
  }
}

// Decoder fully fused (cp.async): out[r] = dot( gelu( cat(z2[eli0[r]],z2[eli1[r]]) @ Wd1 + bd1 ), Wd2 ) + bd2
__global__ __launch_bounds__(256,2)
void wmma_gemm_dec(const int* __restrict__ eli,
                   const float* __restrict__ B,    // Wd1 [256x128]
                   const float* __restrict__ bias, // bd1 [128]
                   const float* __restrict__ Wd2,  // [128]
                   const float* __restrict__ bd2,  // [1]
                   float* __restrict__ out){
  const int K=256, N=128;
  __shared__ float As[2][BM][BK+4];
  __shared__ float Bs[2][BK][BN+4];
  __shared__ float rowsum[128];
  __shared__ float w2s[128];
  __shared__ float bias_s[128];

  int tid=threadIdx.x;
  int warp=tid>>5, lane=tid&31;
  int wm=warp>>1, wn=warp&1;
  int row0=blockIdx.y*BM;

  if(tid<128){ rowsum[tid]=0.f; w2s[tid]=Wd2[tid]; bias_s[tid]=bias[tid]; }

  // per-thread chunk coords + prefetched gather indices (k-invariant per half)
  int ra0=tid>>2, ca=(tid&3)*4;
  int rb0=tid>>5, cb=(tid&31)*4;
  int gr0=row0+ra0, gr1=row0+ra0+64;
  int n00 = (gr0<ELN)? eli[gr0]      : 0;
  int n01 = (gr1<ELN)? eli[gr1]      : 0;
  int n10 = (gr0<ELN)? eli[ELN+gr0]  : 0;
  int n11 = (gr1<ELN)? eli[ELN+gr1]  : 0;

  wmma::fragment<wmma::accumulator,16,16,8,float> acc[2][4];
  #pragma unroll
  for(int i=0;i<2;i++)
    #pragma unroll
    for(int j=0;j<4;j++) wmma::fill_fragment(acc[i][j],0.f);

  #define ISSUE_DEC(st,k0) do{                                                \
    int half=((k0)>=128);                                                     \
    int koff= half? ((k0)-128):(k0);                                          \
    int na = half? n10 : n00;                                                 \
    int nb = half? n11 : n01;                                                 \
    cp16z(SMEM_U32(&As[st][ra0   ][ca]),                                      \
          &g_z2[(size_t)na*128 + koff + ca], gr0<ELN);                        \
    cp16z(SMEM_U32(&As[st][ra0+64][ca]),                                      \
          &g_z2[(size_t)nb*128 + koff + ca], gr1<ELN);                        \
    cp16(SMEM_U32(&Bs[st][rb0  ][cb]),                                        \
         &B[(size_t)((k0)+rb0  )*N + cb]);                                    \
    cp16(SMEM_U32(&Bs[st][rb0+8][cb]),                                        \
         &B[(size_t)((k0)+rb0+8)*N + cb]);                                    \
    CP_COMMIT();                                                              \
  }while(0)

  const int nk=K/BK;   // 16
  ISSUE_DEC(0,0);
  ISSUE_DEC(1,BK);

  for(int kt=0;kt<nk;kt++){
    int cur=kt&1;
    if(kt+1<nk){ CP_WAIT(1); } else { CP_WAIT(0); }
    __syncthreads();
    #pragma unroll
    for(int ks=0;ks<BK;ks+=8){
      wmma::fragment<wmma::matrix_a,16,16,8,wmma::precision::tf32,wmma::row_major> af[2];
      wmma::fragment<wmma::matrix_b,16,16,8,wmma::precision::tf32,wmma::row_major> bf[4];
      #pragma unroll
      for(int i=0;i<2;i++){ wmma::load_matrix_sync(af[i], &As[cur][wm*32+i*16][ks], BK+4); frag_to_tf32(af[i]); }
      #pragma unroll
      for(int j=0;j<4;j++){ wmma::load_matrix_sync(bf[j], &Bs[cur][ks][wn*64+j*16], BN+4); frag_to_tf32(bf[j]); }
      #pragma unroll
      for(int i=0;i<2;i++)
        #pragma unroll
        for(int j=0;j<4;j++) wmma::mma_sync(acc[i][j],af[i],bf[j],acc[i][j]);
    }
    __syncthreads();
    if(kt+2<nk) ISSUE_DEC(cur,(kt+2)*BK);
  }
  #undef ISSUE_DEC

  // epilogue: gelu(acc+bias) dotted with Wd2, per-row reduction (stage via As[0])
  __syncthreads();
  float* St = &As[0][warp*16][0];
  float rowpart=0.f;               // lane owns local row wm*32+lane
  int li = lane>>4;
  int rr = lane&15;
  #pragma unroll
  for(int i=0;i<2;i++)
    #pragma unroll
    for(int j=0;j<4;j++){
      wmma::store_matrix_sync(St, acc[i][j], 20, wmma::mem_row_major);
      __syncwarp();
      if(li==i){
        int c0=wn*64+j*16;
        #pragma unroll
        for(int cc=0;cc<16;cc++){
          int gc=c0+cc;
          rowpart += gelu_t(St[rr*20+cc]+bias_s[gc])*w2s[gc];
        }
      }
      __syncwarp();
    }
  atomicAdd(&rowsum[wm*32+lane], rowpart);
  __syncthreads();
  if(tid<128){
    int gr=row0+tid;
    if(gr<ELN) out[gr]=rowsum[tid]+bd2[0];
  }
}

// ---------------- fused GATv2 layer 1 (H=4, C=128), 2-stream online softmax --
__global__ void gat1_fused(const float* __restrict__ att1, const float* __restrict__ bias1){
  int node=blockIdx.x;
  int w=threadIdx.x>>5, lane=threadIdx.x&31;
  float4 xd = ((const float4*)(g_xr1+(size_t)node*512 + w*128))[lane];
  float4 av = ((const float4*)(att1 + w*128))[lane];
  float m0=-1e30f, s0=0.f, m1=-1e30f, s1=0.f;
  float4 a0={0.f,0.f,0.f,0.f}, a1={0.f,0.f,0.f,0.f};
  int b=g_rowptr[node], en=g_rowptr[node+1];
  int i=b;
  for(; i+1<en; i+=2){
    int src0=g_slist[i], src1=g_slist[i+1];
    float4 x0 = ((const float4*)(g_xl1+(size_t)src0*512 + w*128))[lane];
    float4 x1 = ((const float4*)(g_xl1+(size_t)src1*512 + w*128))[lane];
    float u,p0,p1;
    u=x0.x+xd.x; u=u>0.f?u:0.2f*u; p0 =u*av.x;
    u=x0.y+xd.y; u=u>0.f?u:0.2f*u; p0+=u*av.y;
    u=x0.z+xd.z; u=u>0.f?u:0.2f*u; p0+=u*av.z;
    u=x0.w+xd.w; u=u>0.f?u:0.2f*u; p0+=u*av.w;
    u=x1.x+xd.x; u=u>0.f?u:0.2f*u; p1 =u*av.x;
    u=x1.y+xd.y; u=u>0.f?u:0.2f*u; p1+=u*av.y;
    u=x1.z+xd.z; u=u>0.f?u:0.2f*u; p1+=u*av.z;
    u=x1.w+xd.w; u=u>0.f?u:0.2f*u; p1+=u*av.w;
    #pragma unroll
    for(int o=16;o;o>>=1){
      p0 += __shfl_xor_sync(0xffffffffu,p0,o);
      p1 += __shfl_xor_sync(0xffffffffu,p1,o);
    }
    float nm0=fmaxf(m0,p0), sc0=__expf(m0-nm0), e0=__expf(p0-nm0);
    float nm1=fmaxf(m1,p1), sc1=__expf(m1-nm1), e1=__expf(p1-nm1);
    s0=s0*sc0+e0; s1=s1*sc1+e1;
    a0.x=a0.x*sc0+e0*x0.x; a0.y=a0.y*sc0+e0*x0.y; a0.z=a0.z*sc0+e0*x0.z; a0.w=a0.w*sc0+e0*x0.w;
    a1.x=a1.x*sc1+e1*x1.x; a1.y=a1.y*sc1+e1*x1.y; a1.z=a1.z*sc1+e1*x1.z; a1.w=a1.w*sc1+e1*x1.w;
    m0=nm0; m1=nm1;
  }
  if(i<en){
    int src0=g_slist[i];
    float4 x0 = ((const float4*)(g_xl1+(size_t)src0*512 + w*128))[lane];
    float u,p0;
    u=x0.x+xd.x; u=u>0.f?u:0.2f*u; p0 =u*av.x;
    u=x0.y+xd.y; u=u>0.f?u:0.2f*u; p0+=u*av.y;
    u=x0.z+xd.z; u=u>0.f?u:0.2f*u; p0+=u*av.z;
    u=x0.w+xd.w; u=u>0.f?u:0.2f*u; p0+=u*av.w;
    #pragma unroll
    for(int o=16;o;o>>=1) p0 += __shfl_xor_sync(0xffffffffu,p0,o);
    float nm0=fmaxf(m0,p0), sc0=__expf(m0-nm0), e0=__expf(p0-nm0);
    s0=s0*sc0+e0;
    a0.x=a0.x*sc0+e0*x0.x; a0.y=a0.y*sc0+e0*x0.y; a0.z=a0.z*sc0+e0*x0.z; a0.w=a0.w*sc0+e0*x0.w;
    m0=nm0;
  }
  // merge streams
  float M=fmaxf(m0,m1);
  float c0=__expf(m0-M), c1=__expf(m1-M);
  float S=s0*c0+s1*c1;
  float inv=1.f/S;
  float4 bv = ((const float4*)(bias1 + w*128))[lane];
  float4 o;
  o.x = gelu_t((a0.x*c0+a1.x*c1)*inv + bv.x);
  o.y = gelu_t((a0.y*c0+a1.y*c1)*inv + bv.y);
  o.z = gelu_t((a0.z*c0+a1.z*c1)*inv + bv.z);
  o.w = gelu_t((a0.w*c0+a1.w*c1)*inv + bv.w);
  ((float4*)(g_z1+(size_t)node*512 + w*128))[lane] = o;
}

// ---------------- fused GATv2 layer 2 (H=1, C=128), 4-way split-merge -------
__global__ void gat2_fused(const float* __restrict__ att2, const float* __restrict__ bias2){
  __shared__ float  sm_m[4], sm_s[4];
  __shared__ float4 sm_acc[4][32];
  int node=blockIdx.x;
  int w=threadIdx.x>>5, lane=threadIdx.x&31;
  float4 xd = ((const float4*)(g_xr2+(size_t)node*128))[lane];
  float4 av = ((const float4*)att2)[lane];
  float m=-1e30f, s=0.f;
  float4 acc={0.f,0.f,0.f,0.f};
  int b=g_rowptr[node], en=g_rowptr[node+1];
  for(int i=b+w;i<en;i+=4){
    int src = g_slist[i];
    float4 xs = ((const float4*)(g_xl2+(size_t)src*128))[lane];
    float u,part;
    u=xs.x+xd.x; u=u>0.f?u:0.2f*u; part =u*av.x;
    u=xs.y+xd.y; u=u>0.f?u:0.2f*u; part+=u*av.y;
    u=xs.z+xd.z; u=u>0.f?u:0.2f*u; part+=u*av.z;
    u=xs.w+xd.w; u=u>0.f?u:0.2f*u; part+=u*av.w;
    #pragma unroll
    for(int o=16;o;o>>=1) part += __shfl_xor_sync(0xffffffffu,part,o);
    float nm = fmaxf(m, part);
    float sc = __expf(m - nm);
    float p  = __expf(part - nm);
    s = s*sc + p;
    acc.x = acc.x*sc + p*xs.x;
    acc.y = acc.y*sc + p*xs.y;
    acc.z = acc.z*sc + p*xs.z;
    acc.w = acc.w*sc + p*xs.w;
    m = nm;
  }
  if(lane==0){ sm_m[w]=m; sm_s[w]=s; }
  sm_acc[w][lane]=acc;
  __syncthreads();
  if(w==0){
    float M = fmaxf(fmaxf(sm_m[0],sm_m[1]),fmaxf(sm_m[2],sm_m[3]));
    float S=0.f;
    float4 o={0.f,0.f,0.f,0.f};
    #pragma unroll
    for(int ww=0;ww<4;ww++){
      float sc=__expf(sm_m[ww]-M);
      S += sm_s[ww]*sc;
      float4 a=sm_acc[ww][lane];
      o.x+=a.x*sc; o.y+=a.y*sc; o.z+=a.z*sc; o.w+=a.w*sc;
    }
    float inv=1.f/S;
    float4 bv=((const float4*)bias2)[lane];
    float4 r;
    r.x=o.x*inv+bv.x; r.y=o.y*inv+bv.y; r.z=o.z*inv+bv.z; r.w=o.w*inv+bv.w;
    ((float4*)(g_z2+(size_t)node*128))[lane]=r;
  }
}

// ---------------- launch -----------------------------------------------------
extern "C" void kernel_launch(void* const* d_in, const int* in_sizes, int n_in,
                              void* d_out, int out_size){
  const float* x    =(const float*)d_in[0];
  const int*   ei   =(const int*  )d_in[1];
  const int*   eli  =(const int*  )d_in[2];
  const float* Wl1  =(const float*)d_in[3];
  const float* bl1  =(const float*)d_in[4];
  const float* Wr1  =(const float*)d_in[5];
  const float* br1  =(const float*)d_in[6];
  const float* att1 =(const float*)d_in[7];
  const float* bias1=(const float*)d_in[8];
  const float* Wl2  =(const float*)d_in[9];
  const float* bl2  =(const float*)d_in[10];
  const float* Wr2  =(const float*)d_in[11];
  const float* br2  =(const float*)d_in[12];
  const float* att2 =(const float*)d_in[13];
  const float* bias2=(const float*)d_in[14];
  const float* Wd1  =(const float*)d_in[15];
  const float* bd1  =(const float*)d_in[16];
  const float* Wd2  =(const float*)d_in[17];
  const float* bd2  =(const float*)d_in[18];
  float* out=(float*)d_out;

  float *p_xl1,*p_xr1,*p_z1,*p_xl2,*p_xr2;
  cudaGetSymbolAddress((void**)&p_xl1, g_xl1);
  cudaGetSymbolAddress((void**)&p_xr1, g_xr1);
  cudaGetSymbolAddress((void**)&p_z1 , g_z1 );
  cudaGetSymbolAddress((void**)&p_xl2, g_xl2);
  cudaGetSymbolAddress((void**)&p_xr2, g_xr2);

  // CSR build
  init_kernel   <<<(NN+255)/256,256>>>();
  count_kernel  <<<(ETOT+255)/256,256>>>(ei);
  scan_kernel   <<<1,1024>>>();
  scatter_kernel<<<(ETOT+255)/256,256>>>(ei);

  // layer-1 node transforms: xl1 = x@Wl1+bl1, xr1 = x@Wr1+br1 (shared A)
  wmma_gemm2<<<dim3(512/128,(NN+127)/128,2),256>>>(x, Wl1, bl1, p_xl1, Wr1, br1, p_xr1,
                                                   NN, 256, 512);
  // layer-1 fused attention (online softmax + aggregate + gelu)
  gat1_fused<<<NN,128>>>(att1, bias1);

  // layer-2 node transforms
  wmma_gemm2<<<dim3(1,(NN+127)/128,2),256>>>(p_z1, Wl2, bl2, p_xl2, Wr2, br2, p_xr2,
                                             NN, 512, 128);
  // layer-2 fused attention
  gat2_fused<<<NN,128>>>(att2, bias2);

  // decoder: gather-fused GEMM + gelu + Wd2 dot, all in one kernel
  wmma_gemm_dec<<<dim3(1,(ELN+127)/128),256>>>(eli, Wd1, bd1, Wd2, bd2, out);
}